// round 3
// baseline (speedup 1.0000x reference)
#include <cuda_runtime.h>
#include <cuda_fp16.h>
#include <math.h>

#define B_     4
#define N_     2048
#define F_     16
#define HID_   32
#define H_     6
#define OUT_   16
#define BH_    (B_*H_)
#define CONC_  (H_*HID_)   // 192
#define MAXDEG 256
#define FULL   0xffffffffu

// ---------------- scratch ----------------
__device__ int    g_deg[N_];
__device__ int    g_colsP[(size_t)N_ * MAXDEG];       // padded CSR (2 MB)
__device__ __half g_h1h[(size_t)BH_ * N_ * HID_];     // fp16 features, 3 MB
__device__ float  g_s1[BH_ * N_];
__device__ float  g_s2[BH_ * N_];
__device__ float  g_x1[(size_t)B_ * N_ * CONC_];      // elu(concat heads), fp32
__device__ __half g_h2h[B_ * N_ * OUT_];
__device__ float  g_t1[B_ * N_];
__device__ float  g_t2[B_ * N_];

// ---------------- build padded CSR in one pass ----------------
// edge iff adj[i][j] > 0 || i == j   (adjI = adj + I)
__global__ void k_build(const float* __restrict__ adj) {
    int row  = blockIdx.x * 8 + (threadIdx.x >> 5);
    int lane = threadIdx.x & 31;
    const float* ar = adj + (size_t)row * N_;
    int* dst = g_colsP + (size_t)row * MAXDEG;
    int w = 0;
    for (int base = 0; base < N_; base += 32) {
        int j = base + lane;
        bool pred = (ar[j] > 0.f || j == row);
        unsigned m = __ballot_sync(FULL, pred);
        if (pred) {
            int pos = w + __popc(m & ((1u << lane) - 1u));
            if (pos < MAXDEG) dst[pos] = j;
        }
        w += __popc(m);
    }
    if (lane == 0) g_deg[row] = min(w, MAXDEG);
}

// ---------------- layer 1 linear: warp per (b,n), all 6 heads ----------------
__global__ void k_l1_linear(const float* __restrict__ x,
                            const float* __restrict__ W1,
                            const float* __restrict__ a1) {
    __shared__ float sW[H_ * F_ * HID_];   // 3072 floats, 12 KB, layout == W1
    __shared__ float sa[H_ * 2 * HID_];    // 384 floats
    int tid = threadIdx.x;
    for (int t = tid; t < H_ * F_ * HID_; t += 256) sW[t] = W1[t];
    for (int t = tid; t < H_ * 2 * HID_;  t += 256) sa[t] = a1[t];
    __syncthreads();

    int wslot = tid >> 5, lane = tid & 31;
    int row = blockIdx.x * 8 + wslot;           // 0..8191
    int b = row >> 11, n = row & (N_ - 1);

    float xv = (lane < F_) ? x[(size_t)row * F_ + lane] : 0.f;
    float acc[H_] = {0.f, 0.f, 0.f, 0.f, 0.f, 0.f};
    #pragma unroll
    for (int k = 0; k < F_; k++) {
        float xk = __shfl_sync(FULL, xv, k);
        #pragma unroll
        for (int h = 0; h < H_; h++)
            acc[h] = fmaf(xk, sW[h * F_ * HID_ + k * HID_ + lane], acc[h]);
    }
    #pragma unroll
    for (int h = 0; h < H_; h++) {
        int bh = b * H_ + h;
        g_h1h[((size_t)bh * N_ + n) * HID_ + lane] = __float2half(acc[h]);
        float p1 = acc[h] * sa[h * 2 * HID_ + lane];
        float p2 = acc[h] * sa[h * 2 * HID_ + HID_ + lane];
        #pragma unroll
        for (int d = 16; d; d >>= 1) {
            p1 += __shfl_xor_sync(FULL, p1, d);
            p2 += __shfl_xor_sync(FULL, p2, d);
        }
        if (lane == 0) {
            g_s1[bh * N_ + n] = p1;
            g_s2[bh * N_ + n] = p2;
        }
    }
}

// ---------------- layer 1 sparse attention (L1-resident fp16 gather) ----------------
// grid: 24 bh * 8 chunks = 192 blocks; 8 warps * 32 rows = 256 rows/block
__global__ void k_l1_attn() {
    int bh    = blockIdx.x >> 3;
    int chunk = blockIdx.x & 7;
    int wslot = threadIdx.x >> 5, lane = threadIdx.x & 31;
    int b = bh / H_, h = bh % H_;
    const float*  s2r = g_s2 + bh * N_;
    const __half* hb  = g_h1h + (size_t)bh * N_ * HID_;

    for (int r = 0; r < 32; r++) {
        int i = chunk * 256 + r * 8 + wslot;
        int deg = g_deg[i];
        const int* cols = g_colsP + (size_t)i * MAXDEG;
        float s1i = g_s1[bh * N_ + i];

        // pass 1: row max of LReLU(s1i + s2[j])
        float m = -1e30f;
        for (int t = lane; t < deg; t += 32) {
            float e = s1i + s2r[cols[t]];
            e = e > 0.f ? e : 0.2f * e;
            m = fmaxf(m, e);
        }
        #pragma unroll
        for (int d = 16; d; d >>= 1) m = fmaxf(m, __shfl_xor_sync(FULL, m, d));

        // pass 2: weights on owning lane, shuffle-broadcast, coalesced gather
        float acc0 = 0.f, acc1 = 0.f, den = 0.f;
        for (int base = 0; base < deg; base += 32) {
            int t = base + lane;
            float w = 0.f; int j = 0;
            if (t < deg) {
                j = cols[t];
                float e = s1i + s2r[j];
                e = e > 0.f ? e : 0.2f * e;
                w = __expf(e - m);
            }
            den += w;
            int lim = min(32, deg - base);
            int u = 0;
            for (; u + 2 <= lim; u += 2) {
                float w0 = __shfl_sync(FULL, w, u);
                int   j0 = __shfl_sync(FULL, j, u);
                float w1 = __shfl_sync(FULL, w, u + 1);
                int   j1 = __shfl_sync(FULL, j, u + 1);
                acc0 = fmaf(w0, __half2float(hb[(size_t)j0 * HID_ + lane]), acc0);
                acc1 = fmaf(w1, __half2float(hb[(size_t)j1 * HID_ + lane]), acc1);
            }
            if (u < lim) {
                float w0 = __shfl_sync(FULL, w, u);
                int   j0 = __shfl_sync(FULL, j, u);
                acc0 = fmaf(w0, __half2float(hb[(size_t)j0 * HID_ + lane]), acc0);
            }
        }
        #pragma unroll
        for (int d = 16; d; d >>= 1) den += __shfl_xor_sync(FULL, den, d);
        float v = (acc0 + acc1) / den;
        v = v > 0.f ? v : expm1f(v);   // ELU
        g_x1[((size_t)b * N_ + i) * CONC_ + h * HID_ + lane] = v;
    }
}

// ---------------- layer 2 linear: warp per (b,n), k-split halves ----------------
__global__ void k_l2_linear(const float* __restrict__ W2,
                            const float* __restrict__ a2) {
    __shared__ float sW[CONC_ * OUT_];   // 12 KB, layout == W2 [192][16]
    __shared__ float sa[2 * OUT_];
    int tid = threadIdx.x;
    for (int t = tid; t < CONC_ * OUT_; t += 256) sW[t] = W2[t];
    if (tid < 2 * OUT_) sa[tid] = a2[tid];
    __syncthreads();

    int wslot = tid >> 5, lane = tid & 31;
    int row = blockIdx.x * 8 + wslot;           // 0..8191
    int o = lane & 15, half = lane >> 4;

    const float* xs = g_x1 + (size_t)row * CONC_ + half * 96;
    const float* Ws = sW + half * 96 * OUT_;
    float acc = 0.f;
    #pragma unroll 8
    for (int k = 0; k < 96; k++) acc = fmaf(xs[k], Ws[k * OUT_ + o], acc);
    acc += __shfl_xor_sync(FULL, acc, 16);      // both halves now hold h2[o]

    if (lane < 16) g_h2h[(size_t)row * OUT_ + o] = __float2half(acc);

    // half 0 computes t1 terms, half 1 computes t2 terms
    float p = acc * sa[half * OUT_ + o];
    p += __shfl_xor_sync(FULL, p, 8);
    p += __shfl_xor_sync(FULL, p, 4);
    p += __shfl_xor_sync(FULL, p, 2);
    p += __shfl_xor_sync(FULL, p, 1);
    if ((lane & 15) == 0) {
        if (half == 0) g_t1[row] = p;
        else           g_t2[row] = p;
    }
}

// ---------------- layer 2 sparse attention + ELU + final write ----------------
// grid: 4 b * 32 chunks = 128 blocks; 8 warps * 8 rows = 64 rows/block
__global__ void k_l2_attn(float* __restrict__ out) {
    int b     = blockIdx.x >> 5;
    int chunk = blockIdx.x & 31;
    int wslot = threadIdx.x >> 5, lane = threadIdx.x & 31;
    const float*  s2r = g_t2 + b * N_;
    const __half* hb  = g_h2h + (size_t)b * N_ * OUT_;

    for (int r = 0; r < 8; r++) {
        int i = chunk * 64 + r * 8 + wslot;
        int deg = g_deg[i];
        const int* cols = g_colsP + (size_t)i * MAXDEG;
        float s1i = g_t1[b * N_ + i];

        float m = -1e30f;
        for (int t = lane; t < deg; t += 32) {
            float e = s1i + s2r[cols[t]];
            e = e > 0.f ? e : 0.2f * e;
            m = fmaxf(m, e);
        }
        #pragma unroll
        for (int d = 16; d; d >>= 1) m = fmaxf(m, __shfl_xor_sync(FULL, m, d));

        float acc0 = 0.f, acc1 = 0.f, den = 0.f;
        for (int base = 0; base < deg; base += 32) {
            int t = base + lane;
            float w = 0.f; int j = 0;
            if (t < deg) {
                j = cols[t];
                float e = s1i + s2r[j];
                e = e > 0.f ? e : 0.2f * e;
                w = __expf(e - m);
            }
            den += w;
            int lim = min(32, deg - base);
            int u = 0;
            for (; u + 2 <= lim; u += 2) {
                float w0 = __shfl_sync(FULL, w, u);
                int   j0 = __shfl_sync(FULL, j, u);
                float w1 = __shfl_sync(FULL, w, u + 1);
                int   j1 = __shfl_sync(FULL, j, u + 1);
                if (lane < OUT_) {
                    acc0 = fmaf(w0, __half2float(hb[(size_t)j0 * OUT_ + lane]), acc0);
                    acc1 = fmaf(w1, __half2float(hb[(size_t)j1 * OUT_ + lane]), acc1);
                }
            }
            if (u < lim) {
                float w0 = __shfl_sync(FULL, w, u);
                int   j0 = __shfl_sync(FULL, j, u);
                if (lane < OUT_)
                    acc0 = fmaf(w0, __half2float(hb[(size_t)j0 * OUT_ + lane]), acc0);
            }
        }
        #pragma unroll
        for (int d = 16; d; d >>= 1) den += __shfl_xor_sync(FULL, den, d);
        if (lane < OUT_) {
            float v = (acc0 + acc1) / den;
            v = v > 0.f ? v : expm1f(v);   // ELU
            out[((size_t)b * N_ + i) * OUT_ + lane] = v;
        }
    }
}

// ---------------- launch ----------------
extern "C" void kernel_launch(void* const* d_in, const int* in_sizes, int n_in,
                              void* d_out, int out_size) {
    const float* flow_x = (const float*)d_in[0];   // [4,2048,16]
    const float* adj    = (const float*)d_in[1];   // [2048,2048]
    const float* W1     = (const float*)d_in[2];   // [6,16,32]
    const float* a1     = (const float*)d_in[3];   // [6,64,1]
    const float* W2     = (const float*)d_in[4];   // [192,16]
    const float* a2     = (const float*)d_in[5];   // [32,1]
    float* out = (float*)d_out;

    k_build<<<N_ / 8, 256>>>(adj);
    k_l1_linear<<<B_ * N_ / 8, 256>>>(flow_x, W1, a1);
    k_l1_attn<<<BH_ * 8, 256>>>();
    k_l2_linear<<<B_ * N_ / 8, 256>>>(W2, a2);
    k_l2_attn<<<B_ * 32, 256>>>(out);
}

// round 4
// speedup vs baseline: 3.0035x; 3.0035x over previous
#include <cuda_runtime.h>
#include <cuda_fp16.h>
#include <math.h>

#define B_     4
#define N_     2048
#define F_     16
#define HID_   32
#define H_     6
#define OUT_   16
#define BH_    (B_*H_)
#define CONC_  (H_*HID_)   // 192
#define MAXDEG 256
#define FULL   0xffffffffu

// ---------------- scratch ----------------
__device__ int    g_deg[N_];
__device__ int    g_colsP[(size_t)N_ * MAXDEG];       // padded CSR (2 MB)
__device__ __half g_h1h[(size_t)BH_ * N_ * HID_];     // fp16 features, 3 MB
__device__ float  g_s1[BH_ * N_];
__device__ float  g_s2[BH_ * N_];
__device__ float  g_x1[(size_t)B_ * N_ * CONC_];      // elu(concat heads), fp32
__device__ __half g_h2h[B_ * N_ * OUT_];
__device__ float  g_t1[B_ * N_];
__device__ float  g_t2[B_ * N_];

// ---------------- build padded CSR in one pass ----------------
// edge iff adj[i][j] > 0 || i == j   (adjI = adj + I)
__global__ void k_build(const float* __restrict__ adj) {
    int row  = blockIdx.x * 8 + (threadIdx.x >> 5);
    int lane = threadIdx.x & 31;
    const float* ar = adj + (size_t)row * N_;
    int* dst = g_colsP + (size_t)row * MAXDEG;
    int w = 0;
    for (int base = 0; base < N_; base += 32) {
        int j = base + lane;
        bool pred = (ar[j] > 0.f || j == row);
        unsigned m = __ballot_sync(FULL, pred);
        if (pred) {
            int pos = w + __popc(m & ((1u << lane) - 1u));
            if (pos < MAXDEG) dst[pos] = j;
        }
        w += __popc(m);
    }
    if (lane == 0) g_deg[row] = min(w, MAXDEG);
}

// ---------------- layer 1 linear: warp per (b,n), all 6 heads ----------------
__global__ void k_l1_linear(const float* __restrict__ x,
                            const float* __restrict__ W1,
                            const float* __restrict__ a1) {
    __shared__ float sW[H_ * F_ * HID_];   // 12 KB, layout == W1
    __shared__ float sa[H_ * 2 * HID_];
    int tid = threadIdx.x;
    for (int t = tid; t < H_ * F_ * HID_; t += 256) sW[t] = W1[t];
    for (int t = tid; t < H_ * 2 * HID_;  t += 256) sa[t] = a1[t];
    __syncthreads();

    int wslot = tid >> 5, lane = tid & 31;
    int row = blockIdx.x * 8 + wslot;           // 0..8191
    int b = row >> 11, n = row & (N_ - 1);

    float xv = (lane < F_) ? x[(size_t)row * F_ + lane] : 0.f;
    float acc[H_] = {0.f, 0.f, 0.f, 0.f, 0.f, 0.f};
    #pragma unroll
    for (int k = 0; k < F_; k++) {
        float xk = __shfl_sync(FULL, xv, k);
        #pragma unroll
        for (int h = 0; h < H_; h++)
            acc[h] = fmaf(xk, sW[h * F_ * HID_ + k * HID_ + lane], acc[h]);
    }
    #pragma unroll
    for (int h = 0; h < H_; h++) {
        int bh = b * H_ + h;
        g_h1h[((size_t)bh * N_ + n) * HID_ + lane] = __float2half(acc[h]);
        float p1 = acc[h] * sa[h * 2 * HID_ + lane];
        float p2 = acc[h] * sa[h * 2 * HID_ + HID_ + lane];
        #pragma unroll
        for (int d = 16; d; d >>= 1) {
            p1 += __shfl_xor_sync(FULL, p1, d);
            p2 += __shfl_xor_sync(FULL, p2, d);
        }
        if (lane == 0) {
            g_s1[bh * N_ + n] = p1;
            g_s2[bh * N_ + n] = p2;
        }
    }
}

// ---------------- layer 1 sparse attention: warp per (bh,i), fp16 gather ----------------
#define L1WARPS 8
#define CH 128
__global__ void k_l1_attn() {
    int wslot = threadIdx.x >> 5;
    int lane  = threadIdx.x & 31;
    int gw = blockIdx.x * L1WARPS + wslot;              // one warp per (bh, i)
    int i = gw % N_, bh = gw / N_;                       // consecutive warps share bh
    int b = bh / H_, h = bh % H_;
    int deg = g_deg[i];
    const int* cols = g_colsP + (size_t)i * MAXDEG;
    float s1i = g_s1[bh * N_ + i];
    const float*  s2r = g_s2 + bh * N_;
    const __half* hb  = g_h1h + (size_t)bh * N_ * HID_;

    // pass 1: row max of LReLU(s1i + s2[j])
    float m = -1e30f;
    for (int t = lane; t < deg; t += 32) {
        float e = s1i + s2r[cols[t]];
        e = e > 0.f ? e : 0.2f * e;
        m = fmaxf(m, e);
    }
    #pragma unroll
    for (int d = 16; d; d >>= 1) m = fmaxf(m, __shfl_xor_sync(FULL, m, d));

    // pass 2: chunked weights in smem, coalesced fp16 feature gather
    __shared__ float sw[L1WARPS][CH];
    __shared__ int   sj[L1WARPS][CH];
    float acc0 = 0.f, acc1 = 0.f, den = 0.f;
    for (int base = 0; base < deg; base += CH) {
        int len = min(CH, deg - base);
        for (int t = lane; t < len; t += 32) {
            int j = cols[base + t];
            float e = s1i + s2r[j];
            e = e > 0.f ? e : 0.2f * e;
            float w = __expf(e - m);
            den += w;
            sw[wslot][t] = w;
            sj[wslot][t] = j;
        }
        __syncwarp();
        int t = 0;
        for (; t + 2 <= len; t += 2) {
            acc0 = fmaf(sw[wslot][t],     __half2float(hb[(size_t)sj[wslot][t]     * HID_ + lane]), acc0);
            acc1 = fmaf(sw[wslot][t + 1], __half2float(hb[(size_t)sj[wslot][t + 1] * HID_ + lane]), acc1);
        }
        if (t < len)
            acc0 = fmaf(sw[wslot][t], __half2float(hb[(size_t)sj[wslot][t] * HID_ + lane]), acc0);
        __syncwarp();
    }
    #pragma unroll
    for (int d = 16; d; d >>= 1) den += __shfl_xor_sync(FULL, den, d);
    float v = (acc0 + acc1) / den;
    v = v > 0.f ? v : expm1f(v);                         // ELU
    g_x1[((size_t)b * N_ + i) * CONC_ + h * HID_ + lane] = v;
}

// ---------------- layer 2 linear: block = 32 rows, smem-staged, float4 x ----------------
// grid 256 blocks, block 256: thread = (row r = tid>>3, outputs o0 = (tid&7)*2, o0+1)
__global__ void k_l2_linear(const float* __restrict__ W2,
                            const float* __restrict__ a2) {
    __shared__ float sX[32 * CONC_];     // 24 KB
    __shared__ float sW[CONC_ * OUT_];   // 12 KB, layout == W2 [192][16]
    __shared__ float sa[2 * OUT_];
    int tid = threadIdx.x;
    // stage 32 rows of x1, coalesced float4
    const float4* src = (const float4*)(g_x1 + (size_t)blockIdx.x * 32 * CONC_);
    float4* dst4 = (float4*)sX;
    #pragma unroll
    for (int t = tid; t < 32 * CONC_ / 4; t += 256) dst4[t] = src[t];
    for (int t = tid; t < CONC_ * OUT_; t += 256) sW[t] = W2[t];
    if (tid < 2 * OUT_) sa[tid] = a2[tid];
    __syncthreads();

    int r  = tid >> 3;
    int o0 = (tid & 7) * 2;
    int row = blockIdx.x * 32 + r;

    const float4* xr4 = (const float4*)(sX + r * CONC_);
    float acc0 = 0.f, acc1 = 0.f;
    #pragma unroll 8
    for (int k4 = 0; k4 < CONC_ / 4; k4++) {
        float4 xv = xr4[k4];
        int kb = k4 * 4 * OUT_;
        acc0 = fmaf(xv.x, sW[kb + o0],               acc0);
        acc0 = fmaf(xv.y, sW[kb + OUT_ + o0],        acc0);
        acc0 = fmaf(xv.z, sW[kb + 2 * OUT_ + o0],    acc0);
        acc0 = fmaf(xv.w, sW[kb + 3 * OUT_ + o0],    acc0);
        acc1 = fmaf(xv.x, sW[kb + o0 + 1],           acc1);
        acc1 = fmaf(xv.y, sW[kb + OUT_ + o0 + 1],    acc1);
        acc1 = fmaf(xv.z, sW[kb + 2 * OUT_ + o0 + 1], acc1);
        acc1 = fmaf(xv.w, sW[kb + 3 * OUT_ + o0 + 1], acc1);
    }
    // packed fp16 store of h2[o0], h2[o0+1]
    ((__half2*)g_h2h)[(size_t)row * (OUT_ / 2) + (o0 >> 1)] = __floats2half2_rn(acc0, acc1);

    // t1/t2: reduce over the 8 o-threads of this row (contiguous lanes)
    float p1 = acc0 * sa[o0] + acc1 * sa[o0 + 1];
    float p2 = acc0 * sa[OUT_ + o0] + acc1 * sa[OUT_ + o0 + 1];
    #pragma unroll
    for (int d = 4; d; d >>= 1) {
        p1 += __shfl_xor_sync(FULL, p1, d, 8);
        p2 += __shfl_xor_sync(FULL, p2, d, 8);
    }
    if ((tid & 7) == 0) {
        g_t1[row] = p1;
        g_t2[row] = p2;
    }
}

// ---------------- layer 2 sparse attention + ELU + final write ----------------
// warp per (b,i); gathers 2 neighbors per step (half-warps), fp16 h2
__global__ void k_l2_attn(float* __restrict__ out) {
    int wslot = threadIdx.x >> 5;
    int lane  = threadIdx.x & 31;
    int gw = blockIdx.x * L1WARPS + wslot;               // one warp per (b, i)
    int i = gw % N_, b = gw / N_;
    int deg = g_deg[i];
    const int* cols = g_colsP + (size_t)i * MAXDEG;
    float s1i = g_t1[b * N_ + i];
    const float*  s2r = g_t2 + b * N_;
    const __half* hb  = g_h2h + (size_t)b * N_ * OUT_;

    float m = -1e30f;
    for (int t = lane; t < deg; t += 32) {
        float e = s1i + s2r[cols[t]];
        e = e > 0.f ? e : 0.2f * e;
        m = fmaxf(m, e);
    }
    #pragma unroll
    for (int d = 16; d; d >>= 1) m = fmaxf(m, __shfl_xor_sync(FULL, m, d));

    __shared__ float sw[L1WARPS][CH];
    __shared__ int   sj[L1WARPS][CH];
    int half = lane >> 4, o = lane & 15;
    float acc = 0.f, den = 0.f;
    for (int base = 0; base < deg; base += CH) {
        int len = min(CH, deg - base);
        for (int t = lane; t < len; t += 32) {
            int j = cols[base + t];
            float e = s1i + s2r[j];
            e = e > 0.f ? e : 0.2f * e;
            float w = __expf(e - m);
            den += w;
            sw[wslot][t] = w;
            sj[wslot][t] = j;
        }
        __syncwarp();
        for (int t = 0; t < len; t += 2) {
            int idx = t + half;
            if (idx < len)
                acc = fmaf(sw[wslot][idx],
                           __half2float(hb[(size_t)sj[wslot][idx] * OUT_ + o]), acc);
        }
        __syncwarp();
    }
    #pragma unroll
    for (int d = 16; d; d >>= 1) den += __shfl_xor_sync(FULL, den, d);
    acc += __shfl_xor_sync(FULL, acc, 16);               // combine even/odd neighbor halves
    if (lane < OUT_) {
        float v = acc / den;
        v = v > 0.f ? v : expm1f(v);                     // ELU
        out[((size_t)b * N_ + i) * OUT_ + lane] = v;
    }
}

// ---------------- launch ----------------
extern "C" void kernel_launch(void* const* d_in, const int* in_sizes, int n_in,
                              void* d_out, int out_size) {
    const float* flow_x = (const float*)d_in[0];   // [4,2048,16]
    const float* adj    = (const float*)d_in[1];   // [2048,2048]
    const float* W1     = (const float*)d_in[2];   // [6,16,32]
    const float* a1     = (const float*)d_in[3];   // [6,64,1]
    const float* W2     = (const float*)d_in[4];   // [192,16]
    const float* a2     = (const float*)d_in[5];   // [32,1]
    float* out = (float*)d_out;

    k_build<<<N_ / 8, 256>>>(adj);
    k_l1_linear<<<B_ * N_ / 8, 256>>>(flow_x, W1, a1);
    k_l1_attn<<<BH_ * N_ / L1WARPS, 32 * L1WARPS>>>();
    k_l2_linear<<<B_ * N_ / 32, 256>>>(W2, a2);
    k_l2_attn<<<B_ * N_ / L1WARPS, 32 * L1WARPS>>>(out);
}

// round 5
// speedup vs baseline: 3.3214x; 1.1058x over previous
#include <cuda_runtime.h>
#include <cuda_fp16.h>
#include <math.h>

#define B_     4
#define N_     2048
#define F_     16
#define HID_   32
#define H_     6
#define OUT_   16
#define BN_    (B_*N_)
#define CONC_  (H_*HID_)   // 192
#define MAXDEG 256
#define FULL   0xffffffffu

// ---------------- scratch ----------------
__device__ int     g_deg[N_];
__device__ int     g_colsP[(size_t)N_ * MAXDEG];        // padded CSR (2 MB)
// h1 fp16, 3 half2-planes: plane p holds heads (2p, 2p+1) for [node][lane]
__device__ __half2 g_h1p[3][(size_t)BN_ * HID_];
__device__ float   g_s1f[BN_ * 8];                      // per-node 6 head scores (padded 8)
__device__ float   g_s2f[BN_ * 8];
__device__ float   g_x1[(size_t)BN_ * CONC_];           // elu(concat heads), fp32
__device__ __half  g_h2h[BN_ * OUT_];
__device__ float   g_t1[BN_];
__device__ float   g_t2[BN_];

// ---------------- build padded CSR in one pass ----------------
// edge iff adj[i][j] > 0 || i == j   (adjI = adj + I)
__global__ void k_build(const float* __restrict__ adj) {
    int row  = blockIdx.x * 8 + (threadIdx.x >> 5);
    int lane = threadIdx.x & 31;
    const float* ar = adj + (size_t)row * N_;
    int* dst = g_colsP + (size_t)row * MAXDEG;
    int w = 0;
    for (int base = 0; base < N_; base += 32) {
        int j = base + lane;
        bool pred = (ar[j] > 0.f || j == row);
        unsigned m = __ballot_sync(FULL, pred);
        if (pred) {
            int pos = w + __popc(m & ((1u << lane) - 1u));
            if (pos < MAXDEG) dst[pos] = j;
        }
        w += __popc(m);
    }
    if (lane == 0) g_deg[row] = min(w, MAXDEG);
}

// ---------------- layer 1 linear: warp per (b,n), all 6 heads ----------------
__global__ void k_l1_linear(const float* __restrict__ x,
                            const float* __restrict__ W1,
                            const float* __restrict__ a1) {
    __shared__ float sW[H_ * F_ * HID_];   // 12 KB, layout == W1
    __shared__ float sa[H_ * 2 * HID_];
    int tid = threadIdx.x;
    for (int t = tid; t < H_ * F_ * HID_; t += 256) sW[t] = W1[t];
    for (int t = tid; t < H_ * 2 * HID_;  t += 256) sa[t] = a1[t];
    __syncthreads();

    int wslot = tid >> 5, lane = tid & 31;
    int row = blockIdx.x * 8 + wslot;           // node index 0..BN_-1

    float xv = (lane < F_) ? x[(size_t)row * F_ + lane] : 0.f;
    float acc[H_] = {0.f, 0.f, 0.f, 0.f, 0.f, 0.f};
    #pragma unroll
    for (int k = 0; k < F_; k++) {
        float xk = __shfl_sync(FULL, xv, k);
        #pragma unroll
        for (int h = 0; h < H_; h++)
            acc[h] = fmaf(xk, sW[h * F_ * HID_ + k * HID_ + lane], acc[h]);
    }
    // fp16 plane stores: plane p = heads (2p, 2p+1)
    #pragma unroll
    for (int p = 0; p < 3; p++)
        g_h1p[p][(size_t)row * HID_ + lane] = __floats2half2_rn(acc[2 * p], acc[2 * p + 1]);
    // per-head scores
    #pragma unroll
    for (int h = 0; h < H_; h++) {
        float p1 = acc[h] * sa[h * 2 * HID_ + lane];
        float p2 = acc[h] * sa[h * 2 * HID_ + HID_ + lane];
        #pragma unroll
        for (int d = 16; d; d >>= 1) {
            p1 += __shfl_xor_sync(FULL, p1, d);
            p2 += __shfl_xor_sync(FULL, p2, d);
        }
        if (lane == 0) {
            g_s1f[row * 8 + h] = p1;
            g_s2f[row * 8 + h] = p2;
        }
    }
}

// ---------------- layer 1 attention: ONE warp per (b,i), all 6 heads fused ----------------
#define AW 8
__global__ void k_l1_attn() {
    __shared__ float sw[AW][32][8];    // per-neighbor 6 head weights (padded 8)
    __shared__ int   sj[AW][32];
    int wslot = threadIdx.x >> 5, lane = threadIdx.x & 31;
    int gw = blockIdx.x * AW + wslot;           // warp per (b, i)
    int i = gw & (N_ - 1), b = gw >> 11;
    int node_i = b * N_ + i;
    int deg = g_deg[i];
    const int* cols = g_colsP + (size_t)i * MAXDEG;

    const float4* s1p = (const float4*)(g_s1f + (size_t)node_i * 8);
    float4 sA = s1p[0], sB = s1p[1];
    float s1v[6] = {sA.x, sA.y, sA.z, sA.w, sB.x, sB.y};
    const float* s2base = g_s2f + (size_t)b * N_ * 8;

    float acc[6] = {0.f, 0.f, 0.f, 0.f, 0.f, 0.f};
    float den[6] = {0.f, 0.f, 0.f, 0.f, 0.f, 0.f};

    for (int base = 0; base < deg; base += 32) {
        int lim = min(32, deg - base);
        if (lane < lim) {
            int j = cols[base + lane];
            const float4* sp = (const float4*)(s2base + (size_t)j * 8);
            float4 vA = sp[0], vB = sp[1];
            float s2v[6] = {vA.x, vA.y, vA.z, vA.w, vB.x, vB.y};
            sj[wslot][lane] = j;
            #pragma unroll
            for (int h = 0; h < 6; h++) {
                float e = s1v[h] + s2v[h];
                e = e > 0.f ? e : 0.2f * e;      // LeakyReLU
                float w = __expf(e);             // no max-shift: |e| small, fp32 safe
                den[h] += w;
                sw[wslot][lane][h] = w;
            }
        }
        __syncwarp();
        for (int t = 0; t < lim; t++) {
            size_t nb = (size_t)(b * N_ + sj[wslot][t]) * HID_ + lane;
            float4 w03 = *(const float4*)&sw[wslot][t][0];
            float2 w45 = *(const float2*)&sw[wslot][t][4];
            float2 f0 = __half22float2(g_h1p[0][nb]);
            float2 f1 = __half22float2(g_h1p[1][nb]);
            float2 f2 = __half22float2(g_h1p[2][nb]);
            acc[0] = fmaf(w03.x, f0.x, acc[0]);
            acc[1] = fmaf(w03.y, f0.y, acc[1]);
            acc[2] = fmaf(w03.z, f1.x, acc[2]);
            acc[3] = fmaf(w03.w, f1.y, acc[3]);
            acc[4] = fmaf(w45.x, f2.x, acc[4]);
            acc[5] = fmaf(w45.y, f2.y, acc[5]);
        }
        __syncwarp();
    }
    #pragma unroll
    for (int h = 0; h < 6; h++) {
        #pragma unroll
        for (int d = 16; d; d >>= 1) den[h] += __shfl_xor_sync(FULL, den[h], d);
        float v = acc[h] / den[h];
        v = v > 0.f ? v : expm1f(v);            // ELU
        g_x1[(size_t)node_i * CONC_ + h * HID_ + lane] = v;
    }
}

// ---------------- layer 2 linear: 512 blocks, 16 rows x 16 outputs ----------------
__global__ void k_l2_linear(const float* __restrict__ W2,
                            const float* __restrict__ a2) {
    __shared__ float sX[16 * CONC_];     // 12 KB
    __shared__ float sW[CONC_ * OUT_];   // 12 KB, layout == W2 [192][16]
    __shared__ float sa[2 * OUT_];
    int tid = threadIdx.x;
    const float4* src = (const float4*)(g_x1 + (size_t)blockIdx.x * 16 * CONC_);
    float4* dst4 = (float4*)sX;
    #pragma unroll
    for (int t = tid; t < 16 * CONC_ / 4; t += 256) dst4[t] = src[t];
    for (int t = tid; t < CONC_ * OUT_; t += 256) sW[t] = W2[t];
    if (tid < 2 * OUT_) sa[tid] = a2[tid];
    __syncthreads();

    int r = tid >> 4, o = tid & 15;
    int row = blockIdx.x * 16 + r;

    const float4* xr4 = (const float4*)(sX + r * CONC_);
    float acc = 0.f;
    #pragma unroll 12
    for (int k4 = 0; k4 < CONC_ / 4; k4++) {
        float4 xv = xr4[k4];
        int kb = k4 * 4 * OUT_;
        acc = fmaf(xv.x, sW[kb + o],            acc);
        acc = fmaf(xv.y, sW[kb + OUT_ + o],     acc);
        acc = fmaf(xv.z, sW[kb + 2 * OUT_ + o], acc);
        acc = fmaf(xv.w, sW[kb + 3 * OUT_ + o], acc);
    }
    g_h2h[(size_t)row * OUT_ + o] = __float2half(acc);

    float p1 = acc * sa[o];
    float p2 = acc * sa[OUT_ + o];
    #pragma unroll
    for (int d = 8; d; d >>= 1) {
        p1 += __shfl_xor_sync(FULL, p1, d, 16);
        p2 += __shfl_xor_sync(FULL, p2, d, 16);
    }
    if (o == 0) {
        g_t1[row] = p1;
        g_t2[row] = p2;
    }
}

// ---------------- layer 2 attention + ELU + final write ----------------
__global__ void k_l2_attn(float* __restrict__ out) {
    __shared__ float sw[AW][32];
    __shared__ int   sj[AW][32];
    int wslot = threadIdx.x >> 5, lane = threadIdx.x & 31;
    int gw = blockIdx.x * AW + wslot;           // warp per (b, i)
    int i = gw & (N_ - 1), b = gw >> 11;
    int deg = g_deg[i];
    const int* cols = g_colsP + (size_t)i * MAXDEG;
    float s1i = g_t1[b * N_ + i];
    const float*  s2r = g_t2 + b * N_;
    const __half* hb  = g_h2h + (size_t)b * N_ * OUT_;

    int half = lane >> 4, o = lane & 15;
    float acc = 0.f, den = 0.f;
    for (int base = 0; base < deg; base += 32) {
        int lim = min(32, deg - base);
        if (lane < lim) {
            int j = cols[base + lane];
            float e = s1i + s2r[j];
            e = e > 0.f ? e : 0.2f * e;
            float w = __expf(e);
            den += w;
            sw[wslot][lane] = w;
            sj[wslot][lane] = j;
        }
        __syncwarp();
        for (int t = 0; t < lim; t += 2) {
            int idx = t + half;
            if (idx < lim)
                acc = fmaf(sw[wslot][idx],
                           __half2float(hb[(size_t)sj[wslot][idx] * OUT_ + o]), acc);
        }
        __syncwarp();
    }
    #pragma unroll
    for (int d = 16; d; d >>= 1) den += __shfl_xor_sync(FULL, den, d);
    acc += __shfl_xor_sync(FULL, acc, 16);       // combine even/odd neighbor halves
    if (lane < OUT_) {
        float v = acc / den;
        v = v > 0.f ? v : expm1f(v);             // ELU
        out[((size_t)b * N_ + i) * OUT_ + lane] = v;
    }
}

// ---------------- launch ----------------
extern "C" void kernel_launch(void* const* d_in, const int* in_sizes, int n_in,
                              void* d_out, int out_size) {
    const float* flow_x = (const float*)d_in[0];   // [4,2048,16]
    const float* adj    = (const float*)d_in[1];   // [2048,2048]
    const float* W1     = (const float*)d_in[2];   // [6,16,32]
    const float* a1     = (const float*)d_in[3];   // [6,64,1]
    const float* W2     = (const float*)d_in[4];   // [192,16]
    const float* a2     = (const float*)d_in[5];   // [32,1]
    float* out = (float*)d_out;

    k_build<<<N_ / 8, 256>>>(adj);
    k_l1_linear<<<BN_ / 8, 256>>>(flow_x, W1, a1);
    k_l1_attn<<<BN_ / AW, 32 * AW>>>();
    k_l2_linear<<<BN_ / 16, 256>>>(W2, a2);
    k_l2_attn<<<BN_ / AW, 32 * AW>>>(out);
}

// round 7
// speedup vs baseline: 4.2001x; 1.2646x over previous
#include <cuda_runtime.h>
#include <cuda_fp16.h>
#include <math.h>

#define B_     4
#define N_     2048
#define F_     16
#define HID_   32
#define H_     6
#define OUT_   16
#define BN_    (B_*N_)
#define MAXDEG 256
#define FULL   0xffffffffu

// ---------------- scratch ----------------
__device__ int     g_deg[N_];
__device__ int     g_colsP[(size_t)N_ * MAXDEG];        // padded CSR (2 MB)
// h1 fp16, 3 half2-planes: plane p holds heads (2p, 2p+1), layout [node*32+lane]
__device__ __half2 g_h1p[3][(size_t)BN_ * HID_];
__device__ float   g_s1f[H_ * BN_];                     // [h][node] layout
__device__ float   g_s2f[H_ * BN_];
__device__ __align__(16) __half g_h2h[BN_ * OUT_];
__device__ float   g_t1[BN_];
__device__ float   g_t2[BN_];

// ---------------- build padded CSR in one pass ----------------
__global__ void k_build(const float* __restrict__ adj) {
    int row  = blockIdx.x * 8 + (threadIdx.x >> 5);
    int lane = threadIdx.x & 31;
    const float* ar = adj + (size_t)row * N_;
    int* dst = g_colsP + (size_t)row * MAXDEG;
    int w = 0;
    for (int base = 0; base < N_; base += 32) {
        int j = base + lane;
        bool pred = (ar[j] > 0.f || j == row);
        unsigned m = __ballot_sync(FULL, pred);
        if (pred) {
            int pos = w + __popc(m & ((1u << lane) - 1u));
            if (pos < MAXDEG) dst[pos] = j;
        }
        w += __popc(m);
    }
    if (lane == 0) g_deg[row] = min(w, MAXDEG);
}

// ---------------- layer 1 linear: warp per node, all 6 heads ----------------
__global__ void k_l1_linear(const float* __restrict__ x,
                            const float* __restrict__ W1,
                            const float* __restrict__ a1) {
    __shared__ float sW[H_ * F_ * HID_];   // 12 KB
    __shared__ float sa[H_ * 2 * HID_];
    int tid = threadIdx.x;
    for (int t = tid; t < H_ * F_ * HID_; t += 256) sW[t] = W1[t];
    for (int t = tid; t < H_ * 2 * HID_;  t += 256) sa[t] = a1[t];
    __syncthreads();

    int wslot = tid >> 5, lane = tid & 31;
    int row = blockIdx.x * 8 + wslot;

    float xv = (lane < F_) ? x[(size_t)row * F_ + lane] : 0.f;
    float acc[H_] = {0.f, 0.f, 0.f, 0.f, 0.f, 0.f};
    #pragma unroll
    for (int k = 0; k < F_; k++) {
        float xk = __shfl_sync(FULL, xv, k);
        #pragma unroll
        for (int h = 0; h < H_; h++)
            acc[h] = fmaf(xk, sW[h * F_ * HID_ + k * HID_ + lane], acc[h]);
    }
    #pragma unroll
    for (int p = 0; p < 3; p++)
        g_h1p[p][(size_t)row * HID_ + lane] = __floats2half2_rn(acc[2 * p], acc[2 * p + 1]);
    #pragma unroll
    for (int h = 0; h < H_; h++) {
        float p1 = acc[h] * sa[h * 2 * HID_ + lane];
        float p2 = acc[h] * sa[h * 2 * HID_ + HID_ + lane];
        #pragma unroll
        for (int d = 16; d; d >>= 1) {
            p1 += __shfl_xor_sync(FULL, p1, d);
            p2 += __shfl_xor_sync(FULL, p2, d);
        }
        if (lane == 0) {
            g_s1f[h * BN_ + row] = p1;     // [h][node] layout
            g_s2f[h * BN_ + row] = p2;
        }
    }
}

// ---------------- fused layer-1 attention + ELU + layer-2 linear ----------------
// block = 512 thr = 16 warps = 16 rows of one b. Dynamic smem:
//   [0)      float s2s[6][2048]   49152 B  (scores for this b, all heads)
//   [49152)  float sW2[192*17]    13056 B  (W2 padded stride 17: conflict-free)
//   [62208)  float sa2[32]          128 B
//   [62336)  float sw[16][32][8]  16384 B  (per-neighbor head weights; reused for x1)
//   [78720)  int   sj[16][32]      2048 B
#define SM1_S2  0
#define SM1_W2  49152
#define SM1_A2  62208
#define SM1_SW  62336
#define SM1_SJ  78720
#define SM1_TOT 80768

__global__ void __launch_bounds__(512, 2) k_l1_attn(const float* __restrict__ W2,
                                                    const float* __restrict__ a2) {
    extern __shared__ char smem[];
    float* s2s = (float*)(smem + SM1_S2);
    float* sW2 = (float*)(smem + SM1_W2);
    float* sa2 = (float*)(smem + SM1_A2);
    float (*sw)[32][8] = (float (*)[32][8])(smem + SM1_SW);
    int   (*sj)[32]    = (int (*)[32])(smem + SM1_SJ);

    int tid = threadIdx.x;
    int b  = blockIdx.x >> 7;                 // 128 blocks per b
    int i0 = (blockIdx.x & 127) * 16;

    // stage scores (coalesced: consecutive tid -> consecutive node)
    for (int t = tid; t < H_ * N_; t += 512) {
        int h = t >> 11, n = t & (N_ - 1);
        s2s[t] = g_s2f[h * BN_ + b * N_ + n];
    }
    for (int t = tid; t < 192 * 16; t += 512) sW2[(t >> 4) * 17 + (t & 15)] = W2[t];
    if (tid < 32) sa2[tid] = a2[tid];
    __syncthreads();

    int w = tid >> 5, lane = tid & 31;
    int i = i0 + w;
    int node_i = b * N_ + i;
    int deg = g_deg[i];
    const int* cols = g_colsP + (size_t)i * MAXDEG;

    float s1v[6];
    #pragma unroll
    for (int h = 0; h < 6; h++) s1v[h] = g_s1f[h * BN_ + node_i];

    const __half2* p0 = g_h1p[0];
    const __half2* p1p = g_h1p[1];
    const __half2* p2p = g_h1p[2];

    float acc[6] = {0.f, 0.f, 0.f, 0.f, 0.f, 0.f};
    float den[6] = {0.f, 0.f, 0.f, 0.f, 0.f, 0.f};

    for (int base = 0; base < deg; base += 32) {
        int lim = min(32, deg - base);
        if (lane < lim) {
            int j = cols[base + lane];
            sj[w][lane] = j;
            #pragma unroll
            for (int h = 0; h < 6; h++) {
                float e = s1v[h] + s2s[h * N_ + j];
                e = e > 0.f ? e : 0.2f * e;      // LeakyReLU
                float wt = __expf(e);            // no max-shift (|e| small, fp32 safe)
                den[h] += wt;
                sw[w][lane][h] = wt;
            }
        }
        __syncwarp();
        #define GBODY(T) {                                            \
            int nb = (b * N_ + sj[w][T]) * HID_ + lane;               \
            float4 w03 = *(const float4*)&sw[w][T][0];                \
            float2 w45 = *(const float2*)&sw[w][T][4];                \
            float2 f0 = __half22float2(p0[nb]);                       \
            float2 f1 = __half22float2(p1p[nb]);                      \
            float2 f2 = __half22float2(p2p[nb]);                      \
            acc[0] = fmaf(w03.x, f0.x, acc[0]);                       \
            acc[1] = fmaf(w03.y, f0.y, acc[1]);                       \
            acc[2] = fmaf(w03.z, f1.x, acc[2]);                       \
            acc[3] = fmaf(w03.w, f1.y, acc[3]);                       \
            acc[4] = fmaf(w45.x, f2.x, acc[4]);                       \
            acc[5] = fmaf(w45.y, f2.y, acc[5]); }
        if (lim == 32) {
            #pragma unroll 8
            for (int t = 0; t < 32; t++) GBODY(t)
        } else {
            for (int t = 0; t < lim; t++) GBODY(t)
        }
        #undef GBODY
        __syncwarp();
    }
    #pragma unroll
    for (int h = 0; h < 6; h++) {
        #pragma unroll
        for (int d = 16; d; d >>= 1) den[h] += __shfl_xor_sync(FULL, den[h], d);
    }
    // ELU(x1) into the (now free) sw slice: x1[h*32+lane] = v[h]
    #pragma unroll
    for (int h = 0; h < 6; h++) {
        float v = acc[h] / den[h];
        v = v > 0.f ? v : expm1f(v);
        sw[w][lane][h] = v;
    }
    __syncwarp();

    // layer-2 linear: lane -> output o over a 96-wide k half
    int o = lane & 15, half = lane >> 4;
    int cbase = half * 96;
    float hacc = 0.f;
    #pragma unroll
    for (int c = 0; c < 96; c++) {
        int cc = cbase + c;
        hacc = fmaf(sw[w][cc & 31][cc >> 5], sW2[cc * 17 + o], hacc);
    }
    hacc += __shfl_xor_sync(FULL, hacc, 16);      // combine k-halves: all lanes have h2[o]
    if (lane < 16) g_h2h[node_i * OUT_ + o] = __float2half(hacc);

    float q1 = hacc * sa2[o];
    float q2 = hacc * sa2[OUT_ + o];
    #pragma unroll
    for (int d = 8; d; d >>= 1) {
        q1 += __shfl_xor_sync(FULL, q1, d, 16);
        q2 += __shfl_xor_sync(FULL, q2, d, 16);
    }
    if (lane == 0) {
        g_t1[node_i] = q1;
        g_t2[node_i] = q2;
    }
}

// ---------------- layer-2 attention, all-smem gathers ----------------
// block = 512 thr = 16 rows of one b. Dynamic smem:
//   [0)      __half sh2[2048*16]  65536 B
//   [65536)  float  st2[2048]      8192 B
//   [73728)  float  sw[16][32]     2048 B
//   [75776)  int    sj[16][32]     2048 B
#define SM2_H2  0
#define SM2_T2  65536
#define SM2_SW  73728
#define SM2_SJ  75776
#define SM2_TOT 77824

__global__ void __launch_bounds__(512, 2) k_l2_attn(float* __restrict__ out) {
    extern __shared__ char smem[];
    __half* sh2 = (__half*)(smem + SM2_H2);
    float*  st2 = (float*)(smem + SM2_T2);
    float (*sw)[32] = (float (*)[32])(smem + SM2_SW);
    int   (*sj)[32] = (int (*)[32])(smem + SM2_SJ);

    int tid = threadIdx.x;
    int b  = blockIdx.x >> 7;
    int i0 = (blockIdx.x & 127) * 16;

    // stage h2 (fp16, uint4 copy) and t2 for this b
    {
        const uint4* src = (const uint4*)(g_h2h + (size_t)b * N_ * OUT_);
        uint4* dst = (uint4*)sh2;
        for (int t = tid; t < N_ * OUT_ * 2 / 16; t += 512) dst[t] = src[t];
        for (int t = tid; t < N_; t += 512) st2[t] = g_t2[b * N_ + t];
    }
    __syncthreads();

    int w = tid >> 5, lane = tid & 31;
    int i = i0 + w;
    int node_i = b * N_ + i;
    int deg = g_deg[i];
    const int* cols = g_colsP + (size_t)i * MAXDEG;
    float s1i = g_t1[node_i];

    int o = lane & 15, half = lane >> 4;
    float acc = 0.f, den = 0.f;
    for (int base = 0; base < deg; base += 32) {
        int lim = min(32, deg - base);
        if (lane < lim) {
            int j = cols[base + lane];
            float e = s1i + st2[j];
            e = e > 0.f ? e : 0.2f * e;
            float wt = __expf(e);
            den += wt;
            sw[w][lane] = wt;
            sj[w][lane] = j;
        }
        __syncwarp();
        for (int t = 0; t < lim; t += 2) {
            int idx = t + half;
            if (idx < lim)
                acc = fmaf(sw[w][idx], __half2float(sh2[sj[w][idx] * OUT_ + o]), acc);
        }
        __syncwarp();
    }
    #pragma unroll
    for (int d = 16; d; d >>= 1) den += __shfl_xor_sync(FULL, den, d);
    acc += __shfl_xor_sync(FULL, acc, 16);        // combine even/odd neighbor halves
    if (lane < 16) {
        float v = acc / den;
        v = v > 0.f ? v : expm1f(v);              // ELU
        out[(size_t)node_i * OUT_ + o] = v;
    }
}

// ---------------- launch ----------------
extern "C" void kernel_launch(void* const* d_in, const int* in_sizes, int n_in,
                              void* d_out, int out_size) {
    const float* flow_x = (const float*)d_in[0];   // [4,2048,16]
    const float* adj    = (const float*)d_in[1];   // [2048,2048]
    const float* W1     = (const float*)d_in[2];   // [6,16,32]
    const float* a1     = (const float*)d_in[3];   // [6,64,1]
    const float* W2     = (const float*)d_in[4];   // [192,16]
    const float* a2     = (const float*)d_in[5];   // [32,1]
    float* out = (float*)d_out;

    cudaFuncSetAttribute(k_l1_attn, cudaFuncAttributeMaxDynamicSharedMemorySize, SM1_TOT);
    cudaFuncSetAttribute(k_l2_attn, cudaFuncAttributeMaxDynamicSharedMemorySize, SM2_TOT);

    k_build<<<N_ / 8, 256>>>(adj);
    k_l1_linear<<<BN_ / 8, 256>>>(flow_x, W1, a1);
    k_l1_attn<<<BN_ / 16, 512, SM1_TOT>>>(W2, a2);
    k_l2_attn<<<BN_ / 16, 512, SM2_TOT>>>(out);
}